// round 9
// baseline (speedup 1.0000x reference)
#include <cuda_runtime.h>

#define BATCH   512
#define NCTX    1000
#define DIM     128
#define NHEADS  8
#define HDIM    16
#define HTOT    128
#define CATD    384
#define TILE    128
#define XS      132   // padded stride (floats): conflict-free LDS.128 in both phases

// Scratch: folded query vectors u[b][h][d] (Wk folded into q, scale 1/16 folded in)
__device__ float g_U[BATCH * NHEADS * DIM];

// ---------------------------------------------------------------------------
// Prep: q = state @ Wq^T (per batch), then u[h] = Wk_h^T q_h, scaled by 1/16.
// ---------------------------------------------------------------------------
__global__ __launch_bounds__(128)
void prep_kernel(const float* __restrict__ state,
                 const float* __restrict__ Wq,
                 const float* __restrict__ Wk) {
    __shared__ float st[CATD];
    __shared__ float qs[HTOT];
    int b = blockIdx.x, t = threadIdx.x;

    for (int i = t; i < CATD; i += 128) st[i] = state[(size_t)b * CATD + i];
    __syncthreads();

    {   // q[t] = <state_b, Wq[t,:]>
        const float4* wr = (const float4*)(Wq + (size_t)t * CATD);
        const float4* ss = (const float4*)st;
        float acc = 0.f;
        #pragma unroll
        for (int j = 0; j < CATD / 4; j++) {
            float4 w = wr[j], s = ss[j];
            acc += w.x*s.x + w.y*s.y + w.z*s.z + w.w*s.w;
        }
        qs[t] = acc;
    }
    __syncthreads();

    // u[h][d] for d = t, folded scale 1/hd = 1/16
    #pragma unroll
    for (int h = 0; h < NHEADS; h++) {
        float acc = 0.f;
        #pragma unroll
        for (int j = 0; j < HDIM; j++)
            acc += qs[h * HDIM + j] * Wk[(size_t)(h * HDIM + j) * DIM + t];
        g_U[(size_t)b * (NHEADS * DIM) + h * DIM + t] = acc * 0.0625f;
    }
}

// ---------------------------------------------------------------------------
// Main fused kernel: one CTA per batch, single pass over context.
//  Phase A: scores -> e = exp(s) (no max-sub needed; |s| < ~2), per-head l += e
//  Phase C: c[h][:] += e * x  (rank-1 accumulate, 4 heads per thread)
//  Epilogue: out_h = Wv_h (c_h / l_h); y = Wfc @ out   (all in-block)
// ---------------------------------------------------------------------------
__global__ __launch_bounds__(256)
void attn_kernel(const float* __restrict__ context,
                 const void* __restrict__ mask_raw,   // bool: uint8 / int32 / fp32 — auto-detected
                 const float* __restrict__ Wv,
                 const float* __restrict__ Wfc,
                 float* __restrict__ out) {
    extern __shared__ float X[];                  // [TILE][XS] context tile
    __shared__ float U_s[NHEADS][DIM];
    __shared__ float e_s[NHEADS][TILE];
    __shared__ float l_s[NHEADS];
    __shared__ int   m_s[TILE];
    __shared__ float o_s[HTOT];

    int b = blockIdx.x, t = threadIdx.x;

    // --- Mask-encoding discriminator (deterministic, input-only) ---
    // Word-granular encodings (int32 0/1 or float32 0.0/1.0) have every word in
    // {0, 1, 0x3F800000}. Random 0/1 bytes packed 4-per-word virtually never do.
    const unsigned int* mw = (const unsigned int*)mask_raw;
    const unsigned char* mb8 = (const unsigned char*)mask_raw;
    unsigned int wsamp = mw[t];   // first 256 words exist in every encoding
    bool ok = (wsamp == 0u) || (wsamp == 1u) || (wsamp == 0x3F800000u);
    const bool word_enc = __syncthreads_and((int)ok);

    for (int i = t; i < NHEADS * DIM; i += 256)
        ((float*)U_s)[i] = g_U[(size_t)b * NHEADS * DIM + i];
    if (t < NHEADS) l_s[t] = 0.f;

    // Phase A mapping: 4 heads (hgA*4+i) x 1 token (nA); warp = same hgA -> u broadcast
    const int hgA = t >> 7, nA = t & 127;
    // Phase C mapping: 4 heads (hgC*4+i) x 4 dims (d4*4..) x token-quarter nq
    const int d4 = t & 31, hgC = (t >> 5) & 1, nq = t >> 6;

    float lp0 = 0.f, lp1 = 0.f, lp2 = 0.f, lp3 = 0.f;
    float4 c0 = make_float4(0,0,0,0), c1 = c0, c2 = c0, c3 = c0;

    const float* ctx_b = context + (size_t)b * NCTX * DIM;

    for (int n0 = 0; n0 < NCTX; n0 += TILE) {
        __syncthreads();   // protect X/e_s from previous-iter readers
        // Load tile: 128 tokens x 128 floats, float4, fully coalesced
        #pragma unroll
        for (int r = 0; r < (TILE * DIM / 4) / 256; r++) {   // 16
            int idx = t + r * 256;
            int n = idx >> 5, cc = idx & 31;
            int ng = n0 + n;
            float4 v = make_float4(0,0,0,0);
            if (ng < NCTX) v = ((const float4*)(ctx_b + (size_t)ng * DIM))[cc];
            *((float4*)(X + n * XS + cc * 4)) = v;
        }
        if (t < TILE) {
            int ng = n0 + t;
            int m;
            if (ng >= NCTX)      m = 1;
            else if (word_enc)   m = (mw[(size_t)b * NCTX + ng] != 0u);
            else                 m = (mb8[(size_t)b * NCTX + ng] != 0);
            m_s[t] = m;
        }
        __syncthreads();

        // ---- Phase A: scores for 4 heads of one token (x reused 4x in regs)
        {
            const float4* xr = (const float4*)(X + nA * XS);
            const float4* u0 = (const float4*)U_s[hgA * 4 + 0];
            const float4* u1 = (const float4*)U_s[hgA * 4 + 1];
            const float4* u2 = (const float4*)U_s[hgA * 4 + 2];
            const float4* u3 = (const float4*)U_s[hgA * 4 + 3];
            float s0 = 0.f, s1 = 0.f, s2 = 0.f, s3 = 0.f;
            #pragma unroll
            for (int k = 0; k < DIM / 4; k++) {
                float4 x = xr[k];
                float4 a;
                a = u0[k]; s0 += a.x*x.x + a.y*x.y + a.z*x.z + a.w*x.w;
                a = u1[k]; s1 += a.x*x.x + a.y*x.y + a.z*x.z + a.w*x.w;
                a = u2[k]; s2 += a.x*x.x + a.y*x.y + a.z*x.z + a.w*x.w;
                a = u3[k]; s3 += a.x*x.x + a.y*x.y + a.z*x.z + a.w*x.w;
            }
            float e0, e1, e2, e3;
            if (m_s[nA]) { e0 = e1 = e2 = e3 = 0.f; }
            else {
                e0 = __expf(s0); e1 = __expf(s1);
                e2 = __expf(s2); e3 = __expf(s3);
            }
            e_s[hgA * 4 + 0][nA] = e0;
            e_s[hgA * 4 + 1][nA] = e1;
            e_s[hgA * 4 + 2][nA] = e2;
            e_s[hgA * 4 + 3][nA] = e3;
            lp0 += e0; lp1 += e1; lp2 += e2; lp3 += e3;
        }
        __syncthreads();

        // ---- Phase C: c[h] += e * x for 4 heads (x reused 4x), token quarter
        {
            const float* e0 = e_s[hgC * 4 + 0];
            const float* e1 = e_s[hgC * 4 + 1];
            const float* e2 = e_s[hgC * 4 + 2];
            const float* e3 = e_s[hgC * 4 + 3];
            int nbase = nq * 32;
            #pragma unroll 8
            for (int j = 0; j < 32; j++) {
                int nn = nbase + j;
                float4 x = *((const float4*)(X + nn * XS + d4 * 4));
                float w;
                w = e0[nn]; c0.x += w*x.x; c0.y += w*x.y; c0.z += w*x.z; c0.w += w*x.w;
                w = e1[nn]; c1.x += w*x.x; c1.y += w*x.y; c1.z += w*x.z; c1.w += w*x.w;
                w = e2[nn]; c2.x += w*x.x; c2.y += w*x.y; c2.z += w*x.z; c2.w += w*x.w;
                w = e3[nn]; c3.x += w*x.x; c3.y += w*x.y; c3.z += w*x.z; c3.w += w*x.w;
            }
        }
    }

    // Reduce l per head (one hgA per warp -> warp-reduce + shared atomic)
    {
        float v;
        v = lp0;
        #pragma unroll
        for (int o = 16; o > 0; o >>= 1) v += __shfl_xor_sync(0xffffffffu, v, o);
        if ((t & 31) == 0) atomicAdd(&l_s[hgA * 4 + 0], v);
        v = lp1;
        #pragma unroll
        for (int o = 16; o > 0; o >>= 1) v += __shfl_xor_sync(0xffffffffu, v, o);
        if ((t & 31) == 0) atomicAdd(&l_s[hgA * 4 + 1], v);
        v = lp2;
        #pragma unroll
        for (int o = 16; o > 0; o >>= 1) v += __shfl_xor_sync(0xffffffffu, v, o);
        if ((t & 31) == 0) atomicAdd(&l_s[hgA * 4 + 2], v);
        v = lp3;
        #pragma unroll
        for (int o = 16; o > 0; o >>= 1) v += __shfl_xor_sync(0xffffffffu, v, o);
        if ((t & 31) == 0) atomicAdd(&l_s[hgA * 4 + 3], v);
    }
    __syncthreads();   // phase-C X reads + l atomics complete

    // Reduce the 4 nq-partials of C; reuse X smem as scratch.
    {
        float* Cp = X;   // partials: [nq][h][d] = nq*1024 + h*128 + d
        *((float4*)(Cp + (nq * NHEADS + hgC * 4 + 0) * DIM + d4 * 4)) = c0;
        *((float4*)(Cp + (nq * NHEADS + hgC * 4 + 1) * DIM + d4 * 4)) = c1;
        *((float4*)(Cp + (nq * NHEADS + hgC * 4 + 2) * DIM + d4 * 4)) = c2;
        *((float4*)(Cp + (nq * NHEADS + hgC * 4 + 3) * DIM + d4 * 4)) = c3;
    }
    __syncthreads();
    float* Cfin = X + 4096;   // disjoint from partial region [0,4096)
    for (int i = t; i < NHEADS * DIM; i += 256)
        Cfin[i] = X[i] + X[1024 + i] + X[2048 + i] + X[3072 + i];
    __syncthreads();

    // o[t] = <Wv[t,:], c_h>/l_h  for t = h*16+j  (matches head-concat order)
    if (t < HTOT) {
        int h = t >> 4;
        const float4* wv = (const float4*)(Wv + (size_t)t * DIM);
        const float4* cf = (const float4*)(Cfin + h * DIM);
        float acc = 0.f;
        #pragma unroll
        for (int k = 0; k < DIM / 4; k++) {
            float4 w = wv[k], cc4 = cf[k];
            acc += w.x*cc4.x + w.y*cc4.y + w.z*cc4.z + w.w*cc4.w;
        }
        o_s[t] = acc / l_s[h];
    }
    __syncthreads();
    // y[b][t] = <Wfc[t,:], o>
    if (t < HTOT) {
        const float4* wf = (const float4*)(Wfc + (size_t)t * DIM);
        const float4* oo = (const float4*)o_s;
        float acc = 0.f;
        #pragma unroll
        for (int k = 0; k < DIM / 4; k++) {
            float4 w = wf[k], o4 = oo[k];
            acc += w.x*o4.x + w.y*o4.y + w.z*o4.z + w.w*o4.w;
        }
        out[(size_t)b * HTOT + t] = acc;
    }
}

// ---------------------------------------------------------------------------
extern "C" void kernel_launch(void* const* d_in, const int* in_sizes, int n_in,
                              void* d_out, int out_size) {
    const float* state   = (const float*)d_in[0];
    const float* context = (const float*)d_in[1];
    const void*  mask    = d_in[2];                 // encoding auto-detected in-kernel
    const float* Wq      = (const float*)d_in[3];
    const float* Wk      = (const float*)d_in[4];
    const float* Wv      = (const float*)d_in[5];
    const float* Wfc     = (const float*)d_in[6];
    float*       out     = (float*)d_out;

    const int dyn_smem = TILE * XS * sizeof(float);   // 67584 B > 48KB default
    cudaFuncSetAttribute(attn_kernel,
                         cudaFuncAttributeMaxDynamicSharedMemorySize, dyn_smem);

    prep_kernel<<<BATCH, 128>>>(state, Wq, Wk);
    attn_kernel<<<BATCH, 256, dyn_smem>>>(context, mask, Wv, Wfc, out);
}

// round 12
// speedup vs baseline: 1.0824x; 1.0824x over previous
#include <cuda_runtime.h>

#define BATCH   512
#define NCTX    1000
#define DIM     128
#define NHEADS  8
#define HDIM    16
#define HTOT    128
#define CATD    384
#define TILE    64
#define XS      132   // padded row stride (floats): conflict-free LDS.128
#define BPREP   8     // batches per prep CTA

// Scratch: folded query vectors u[b][h][d] (Wk folded into q, scale 1/16 folded in)
__device__ float g_U[BATCH * NHEADS * DIM];

// ---------------------------------------------------------------------------
// Prep (batched): 8 batches per CTA so Wq/Wk rows are L1-reused 8x.
// q[b] = state[b] @ Wq^T ; u[b][h] = Wk_h^T q[b][h] * (1/16)
// ---------------------------------------------------------------------------
__global__ __launch_bounds__(128)
void prep_kernel(const float* __restrict__ state,
                 const float* __restrict__ Wq,
                 const float* __restrict__ Wk) {
    __shared__ float st[BPREP][CATD];
    __shared__ float qs[BPREP][HTOT];
    int b0 = blockIdx.x * BPREP, t = threadIdx.x;

    // load 8 states (8*384 floats) coalesced
    for (int i = t; i < BPREP * CATD / 4; i += 128) {
        ((float4*)&st[0][0])[i] =
            ((const float4*)(state + (size_t)b0 * CATD))[i];
    }
    __syncthreads();

    {   // q[b][t] = <state_b, Wq[t,:]> ; Wq row streamed once, reused 8x
        const float4* wr = (const float4*)(Wq + (size_t)t * CATD);
        float acc[BPREP];
        #pragma unroll
        for (int b = 0; b < BPREP; b++) acc[b] = 0.f;
        for (int j = 0; j < CATD / 4; j++) {
            float4 w = wr[j];
            #pragma unroll
            for (int b = 0; b < BPREP; b++) {
                float4 s = ((const float4*)st[b])[j];
                acc[b] += w.x*s.x + w.y*s.y + w.z*s.z + w.w*s.w;
            }
        }
        #pragma unroll
        for (int b = 0; b < BPREP; b++) qs[b][t] = acc[b];
    }
    __syncthreads();

    // u[b][h][d=t] = sum_j qs[b][h*16+j] * Wk[h*16+j][t], *1/16
    for (int h = 0; h < NHEADS; h++) {
        float wk[HDIM];
        #pragma unroll
        for (int j = 0; j < HDIM; j++)
            wk[j] = Wk[(size_t)(h * HDIM + j) * DIM + t];
        #pragma unroll
        for (int b = 0; b < BPREP; b++) {
            float acc = 0.f;
            #pragma unroll
            for (int j = 0; j < HDIM; j++) acc += qs[b][h * HDIM + j] * wk[j];
            g_U[(size_t)(b0 + b) * (NHEADS * DIM) + h * DIM + t] = acc * 0.0625f;
        }
    }
}

// ---------------------------------------------------------------------------
// Main fused kernel. TILE=64, 4 CTAs/SM target.
//  Phase A (threads 0-127): 2 head-groups x 64 tokens, 4 heads/thread.
//  Phase C (all 256):       (32 dim-chunks) x (2 hg) x (4 token-quarters).
//  e_s packed [token][8 heads] -> phase C reads 4 heads per LDS.128 broadcast.
// ---------------------------------------------------------------------------
__global__ __launch_bounds__(256, 4)
void attn_kernel(const float* __restrict__ context,
                 const void* __restrict__ mask_raw,   // uint8 / int32 / fp32 bool
                 const float* __restrict__ Wv,
                 const float* __restrict__ Wfc,
                 float* __restrict__ out) {
    extern __shared__ float X[];                  // [TILE][XS]
    __shared__ float U_s[NHEADS][DIM];
    __shared__ float e_s[TILE][NHEADS];           // packed by token
    __shared__ float l_s[NHEADS];
    __shared__ float o_s[HTOT];

    int b = blockIdx.x, t = threadIdx.x;

    // mask-encoding discriminator (word: every word in {0,1,0x3F800000})
    const unsigned int*  mw  = (const unsigned int*)mask_raw;
    const unsigned char* mb8 = (const unsigned char*)mask_raw;
    unsigned int wsamp = mw[t];
    bool okw = (wsamp == 0u) || (wsamp == 1u) || (wsamp == 0x3F800000u);
    const bool word_enc = __syncthreads_and((int)okw);

    for (int i = t; i < NHEADS * DIM; i += 256)
        ((float*)U_s)[i] = g_U[(size_t)b * NHEADS * DIM + i];
    if (t < NHEADS) l_s[t] = 0.f;

    const int hgA = t >> 6, nA = t & 63;          // phase A: valid for t<128
    const int d4 = t & 31, hgC = (t >> 5) & 1, nq = t >> 6;  // phase C

    float lp0 = 0.f, lp1 = 0.f, lp2 = 0.f, lp3 = 0.f;
    float4 c0 = make_float4(0,0,0,0), c1 = c0, c2 = c0, c3 = c0;

    const float* ctx_b = context + (size_t)b * NCTX * DIM;

    for (int n0 = 0; n0 < NCTX; n0 += TILE) {
        __syncthreads();   // protect X/e_s from previous-iteration readers
        // load tile: 64 tokens x 128 floats (2048 float4 / 256 thr = 8 iters)
        #pragma unroll 4
        for (int r = 0; r < (TILE * DIM / 4) / 256; r++) {
            int idx = t + r * 256;
            int n = idx >> 5, cc = idx & 31;
            int ng = n0 + n;
            float4 v = make_float4(0,0,0,0);
            if (ng < NCTX) v = ((const float4*)(ctx_b + (size_t)ng * DIM))[cc];
            *((float4*)(X + n * XS + cc * 4)) = v;
        }
        __syncthreads();

        // ---- Phase A (t < 128): 4 heads of one token
        if (t < 128) {
            int ng = n0 + nA;
            int m = 1;
            if (ng < NCTX)
                m = word_enc ? (mw[(size_t)b * NCTX + ng] != 0u)
                             : (mb8[(size_t)b * NCTX + ng] != 0);

            const float4* xr = (const float4*)(X + nA * XS);
            const float4* u0 = (const float4*)U_s[hgA * 4 + 0];
            const float4* u1 = (const float4*)U_s[hgA * 4 + 1];
            const float4* u2 = (const float4*)U_s[hgA * 4 + 2];
            const float4* u3 = (const float4*)U_s[hgA * 4 + 3];
            float s0 = 0.f, s1 = 0.f, s2 = 0.f, s3 = 0.f;
            #pragma unroll
            for (int k = 0; k < DIM / 4; k++) {
                float4 x = xr[k];
                float4 a;
                a = u0[k]; s0 += a.x*x.x + a.y*x.y + a.z*x.z + a.w*x.w;
                a = u1[k]; s1 += a.x*x.x + a.y*x.y + a.z*x.z + a.w*x.w;
                a = u2[k]; s2 += a.x*x.x + a.y*x.y + a.z*x.z + a.w*x.w;
                a = u3[k]; s3 += a.x*x.x + a.y*x.y + a.z*x.z + a.w*x.w;
            }
            float4 e;
            if (m) { e = make_float4(0.f, 0.f, 0.f, 0.f); }
            else {
                e.x = __expf(s0); e.y = __expf(s1);
                e.z = __expf(s2); e.w = __expf(s3);
            }
            *((float4*)&e_s[nA][hgA * 4]) = e;
            lp0 += e.x; lp1 += e.y; lp2 += e.z; lp3 += e.w;
        }
        __syncthreads();

        // ---- Phase C: c[h] += e * x ; 4 heads, 4 dims, 16-token quarter
        {
            int nbase = nq * 16;
            #pragma unroll 8
            for (int j = 0; j < 16; j++) {
                int nn = nbase + j;
                float4 x = *((const float4*)(X + nn * XS + d4 * 4));
                float4 e = *((const float4*)&e_s[nn][hgC * 4]);
                c0.x += e.x*x.x; c0.y += e.x*x.y; c0.z += e.x*x.z; c0.w += e.x*x.w;
                c1.x += e.y*x.x; c1.y += e.y*x.y; c1.z += e.y*x.z; c1.w += e.y*x.w;
                c2.x += e.z*x.x; c2.y += e.z*x.y; c2.z += e.z*x.z; c2.w += e.z*x.w;
                c3.x += e.w*x.x; c3.y += e.w*x.y; c3.z += e.w*x.z; c3.w += e.w*x.w;
            }
        }
    }

    // Reduce l per head. Inactive phase-A warps contribute zeros (harmless).
    {
        const int hl = (t >> 6) & 1;   // safe head-group index for all threads
        float v;
        v = lp0;
        #pragma unroll
        for (int o = 16; o > 0; o >>= 1) v += __shfl_xor_sync(0xffffffffu, v, o);
        if ((t & 31) == 0) atomicAdd(&l_s[hl * 4 + 0], v);
        v = lp1;
        #pragma unroll
        for (int o = 16; o > 0; o >>= 1) v += __shfl_xor_sync(0xffffffffu, v, o);
        if ((t & 31) == 0) atomicAdd(&l_s[hl * 4 + 1], v);
        v = lp2;
        #pragma unroll
        for (int o = 16; o > 0; o >>= 1) v += __shfl_xor_sync(0xffffffffu, v, o);
        if ((t & 31) == 0) atomicAdd(&l_s[hl * 4 + 2], v);
        v = lp3;
        #pragma unroll
        for (int o = 16; o > 0; o >>= 1) v += __shfl_xor_sync(0xffffffffu, v, o);
        if ((t & 31) == 0) atomicAdd(&l_s[hl * 4 + 3], v);
    }
    __syncthreads();   // phase-C X reads + l atomics complete

    // Reduce the 4 nq-partials of C; reuse X smem as scratch.
    {
        float* Cp = X;   // partials: [nq][h][d] = nq*1024 + h*128 + d
        *((float4*)(Cp + (nq * NHEADS + hgC * 4 + 0) * DIM + d4 * 4)) = c0;
        *((float4*)(Cp + (nq * NHEADS + hgC * 4 + 1) * DIM + d4 * 4)) = c1;
        *((float4*)(Cp + (nq * NHEADS + hgC * 4 + 2) * DIM + d4 * 4)) = c2;
        *((float4*)(Cp + (nq * NHEADS + hgC * 4 + 3) * DIM + d4 * 4)) = c3;
    }
    __syncthreads();
    float* Cfin = X + 4096;   // disjoint from partial region [0,4096); X has 8448
    for (int i = t; i < NHEADS * DIM; i += 256)
        Cfin[i] = X[i] + X[1024 + i] + X[2048 + i] + X[3072 + i];
    __syncthreads();

    // o[t] = <Wv[t,:], c_h>/l_h  for t = h*16+j  (head-concat order)
    if (t < HTOT) {
        int h = t >> 4;
        const float4* wv = (const float4*)(Wv + (size_t)t * DIM);
        const float4* cf = (const float4*)(Cfin + h * DIM);
        float acc = 0.f;
        #pragma unroll
        for (int k = 0; k < DIM / 4; k++) {
            float4 w = wv[k], cc4 = cf[k];
            acc += w.x*cc4.x + w.y*cc4.y + w.z*cc4.z + w.w*cc4.w;
        }
        o_s[t] = acc / l_s[h];
    }
    __syncthreads();
    // y[b][t] = <Wfc[t,:], o>
    if (t < HTOT) {
        const float4* wf = (const float4*)(Wfc + (size_t)t * DIM);
        const float4* oo = (const float4*)o_s;
        float acc = 0.f;
        #pragma unroll
        for (int k = 0; k < DIM / 4; k++) {
            float4 w = wf[k], o4 = oo[k];
            acc += w.x*o4.x + w.y*o4.y + w.z*o4.z + w.w*o4.w;
        }
        out[(size_t)b * HTOT + t] = acc;
    }
}

// ---------------------------------------------------------------------------
extern "C" void kernel_launch(void* const* d_in, const int* in_sizes, int n_in,
                              void* d_out, int out_size) {
    const float* state   = (const float*)d_in[0];
    const float* context = (const float*)d_in[1];
    const void*  mask    = d_in[2];                 // encoding auto-detected
    const float* Wq      = (const float*)d_in[3];
    const float* Wk      = (const float*)d_in[4];
    const float* Wv      = (const float*)d_in[5];
    const float* Wfc     = (const float*)d_in[6];
    float*       out     = (float*)d_out;

    const int dyn_smem = TILE * XS * sizeof(float);   // 33792 B (< 48KB default)

    prep_kernel<<<BATCH / BPREP, 128>>>(state, Wq, Wk);
    attn_kernel<<<BATCH, 256, dyn_smem>>>(context, mask, Wv, Wfc, out);
}